// round 13
// baseline (speedup 1.0000x reference)
#include <cuda_runtime.h>
#include <math.h>
#include <stdint.h>

// N=200000, D=512, H=256, K=64.
// prep -> fused (score mma tf32 + exp + pool mma tf32; e read from DRAM once)
// -> reduce -> final.
#define NN 200000
#define DD 512
#define KK 64
#define HH 256
#define SCALE 0.0625f
#define NT 1563             // ceil(200000/128)
#define SGRID 148
// fused smem layout (floats)
#define PA_S 516
#define PB_OFF 33024
#define PB_S 68
#define ES_OFF 41728
#define ES_S 36
#define ES_BUF 4608
#define QS_OFF 50944
#define QS_S 36
#define QS_BUF 2304
#define FS_SMEM 222208      // 55552 floats (+2304 B static < 227 KB cap)

__device__ __align__(256) float g_qWk[KK * DD];     // [k][d]
__device__ __align__(256) float g_qbk[KK];
__device__ __align__(256) float g_sumpart[SGRID * KK];
__device__ __align__(256) float g_part2[(size_t)SGRID * KK * DD];
__device__ __align__(256) float g_pooled[KK * DD];

__device__ __forceinline__ void mma8(float* c, const uint32_t* a, const uint32_t* b) {
    asm volatile(
        "mma.sync.aligned.m16n8k8.row.col.f32.tf32.tf32.f32 "
        "{%0,%1,%2,%3}, {%4,%5,%6,%7}, {%8,%9}, {%0,%1,%2,%3};"
        : "+f"(c[0]), "+f"(c[1]), "+f"(c[2]), "+f"(c[3])
        : "r"(a[0]), "r"(a[1]), "r"(a[2]), "r"(a[3]), "r"(b[0]), "r"(b[1]));
}
__device__ __forceinline__ void cpa16(uint32_t dst, const void* src) {
    asm volatile("cp.async.cg.shared.global [%0], [%1], 16;" :: "r"(dst), "l"(src));
}
__device__ __forceinline__ uint32_t smem_u32(const void* p) {
    uint32_t a; asm("{ .reg .u64 t; cvta.to.shared.u64 t, %1; cvt.u32.u64 %0, t; }" : "=r"(a) : "l"(p)); return a;
}

// ---- K0: prep ----
__global__ __launch_bounds__(512) void prep_kernel(const float* __restrict__ q,
                                                   const float* __restrict__ Wk,
                                                   const float* __restrict__ bk) {
    const int k = blockIdx.x, t = threadIdx.x;
    __shared__ float qs[HH]; __shared__ float red[256];
    if (t < HH) qs[t] = q[k * HH + t];
    __syncthreads();
    const float* w = Wk + (size_t)k * HH * DD + t;
    float acc = 0.f;
#pragma unroll 8
    for (int h = 0; h < HH; h++) acc += qs[h] * w[(size_t)h * DD];
    g_qWk[k * DD + t] = acc;
    if (t < HH) red[t] = qs[t] * bk[k * HH + t];
    __syncthreads();
    for (int o = 128; o > 0; o >>= 1) { if (t < o) red[t] += red[t + o]; __syncthreads(); }
    if (t == 0) g_qbk[k] = red[0];
}

// ---- K1: fused score+exp+pool ----
__global__ __launch_bounds__(512, 1) void fused_kernel(const float* __restrict__ e) {
    extern __shared__ float sm[];
    float* pa = sm;                 // pool accumulator [64][516]
    float* Pb = sm + PB_OFF;        // P tile [128][68]
    const uint32_t sbase = smem_u32(sm);
    __shared__ float sbk[KK];
    __shared__ float sums[16][32];
    const int t = threadIdx.x, w = t >> 5, lane = t & 31;
    const int lq = lane >> 2, lr = lane & 3;
    const int hw = w & 7, hh = w >> 3;      // phase1: m-row block, head-half
    const int mt = w & 3, nt2 = w >> 2;     // phase2: head m-tile, d n-tile
    if (t < KK) sbk[t] = g_qbk[t] * SCALE;
#pragma unroll
    for (int j = 0; j < 65; j++) {
        int idx = t + j * 512;
        if (idx < 64 * PA_S) pa[idx] = 0.f;
    }
    __syncthreads();

    float sumacc[4][2];
#pragma unroll
    for (int nt = 0; nt < 4; nt++) { sumacc[nt][0] = 0.f; sumacc[nt][1] = 0.f; }

    for (int tile = blockIdx.x; tile < NT; tile += SGRID) {
        const int n0 = tile * 128;
        // ---- phase 1: scores ----
        {
#pragma unroll
            for (int j = 0; j < 2; j++) {
                int idx = t + j * 512, row = idx >> 3, qd = idx & 7;
                int gn = n0 + row, off = ES_OFF + row * ES_S + qd * 4;
                if (gn < NN) cpa16(sbase + off * 4, e + (size_t)gn * DD + qd * 4);
                else *(float4*)(sm + off) = make_float4(0.f, 0.f, 0.f, 0.f);
            }
            int head = t >> 3, qd = t & 7, off = QS_OFF + head * QS_S + qd * 4;
            cpa16(sbase + off * 4, g_qWk + head * DD + qd * 4);
            asm volatile("cp.async.commit_group;" ::: "memory");
        }
        float acc[4][4];
#pragma unroll
        for (int nt = 0; nt < 4; nt++)
#pragma unroll
            for (int i = 0; i < 4; i++) acc[nt][i] = 0.f;

        for (int c = 0; c < 16; c++) {
            if (c < 15) {
                const int b = (c + 1) & 1;
#pragma unroll
                for (int j = 0; j < 2; j++) {
                    int idx = t + j * 512, row = idx >> 3, qd = idx & 7;
                    int gn = n0 + row, off = ES_OFF + b * ES_BUF + row * ES_S + qd * 4;
                    if (gn < NN) cpa16(sbase + off * 4, e + (size_t)gn * DD + (c + 1) * 32 + qd * 4);
                    else *(float4*)(sm + off) = make_float4(0.f, 0.f, 0.f, 0.f);
                }
                int head = t >> 3, qd = t & 7;
                int off = QS_OFF + b * QS_BUF + head * QS_S + qd * 4;
                cpa16(sbase + off * 4, g_qWk + head * DD + (c + 1) * 32 + qd * 4);
                asm volatile("cp.async.commit_group;" ::: "memory");
                asm volatile("cp.async.wait_group 1;" ::: "memory");
            } else {
                asm volatile("cp.async.wait_group 0;" ::: "memory");
            }
            __syncthreads();
            const float* Es = sm + ES_OFF + (c & 1) * ES_BUF;
            const float* Qs = sm + QS_OFF + (c & 1) * QS_BUF;
#pragma unroll
            for (int s = 0; s < 4; s++) {
                uint32_t A[4], B[4][2];
                const int ar = (hw * 16 + lq) * ES_S + s * 8 + lr;
                A[0] = __float_as_uint(Es[ar]);
                A[1] = __float_as_uint(Es[ar + 8 * ES_S]);
                A[2] = __float_as_uint(Es[ar + 4]);
                A[3] = __float_as_uint(Es[ar + 8 * ES_S + 4]);
#pragma unroll
                for (int nt = 0; nt < 4; nt++) {
                    int hrow = (hh * 32 + nt * 8 + lq) * QS_S + s * 8 + lr;
                    B[nt][0] = __float_as_uint(Qs[hrow]);
                    B[nt][1] = __float_as_uint(Qs[hrow + 4]);
                }
#pragma unroll
                for (int nt = 0; nt < 4; nt++) mma8(acc[nt], A, B[nt]);
            }
            __syncthreads();
        }
        // epilogue: exp -> Pbuf + sums
        {
            const int r0 = hw * 16 + lq, r1 = r0 + 8;
            const bool ok0 = (n0 + r0) < NN, ok1 = (n0 + r1) < NN;
#pragma unroll
            for (int nt = 0; nt < 4; nt++) {
                const int h = hh * 32 + nt * 8 + 2 * lr;
                const float b0 = sbk[h], b1 = sbk[h + 1];
                float p0 = 0.f, p1 = 0.f, p2 = 0.f, p3 = 0.f;
                if (ok0) {
                    p0 = __expf(acc[nt][0] * SCALE + b0);
                    p1 = __expf(acc[nt][1] * SCALE + b1);
                }
                if (ok1) {
                    p2 = __expf(acc[nt][2] * SCALE + b0);
                    p3 = __expf(acc[nt][3] * SCALE + b1);
                }
                *(float2*)(Pb + r0 * PB_S + h) = make_float2(p0, p1);
                *(float2*)(Pb + r1 * PB_S + h) = make_float2(p2, p3);
                sumacc[nt][0] += p0 + p2;
                sumacc[nt][1] += p1 + p3;
            }
        }
        __syncthreads();
        // ---- phase 2: pool (e re-read hits L2) ----
        {
#pragma unroll
            for (int j = 0; j < 2; j++) {
                int idx = t + j * 512, row = idx >> 3, qd = idx & 7;
                int gn = n0 + row, off = ES_OFF + row * ES_S + qd * 4;
                if (gn < NN) cpa16(sbase + off * 4, e + (size_t)gn * DD + qd * 4);
                else *(float4*)(sm + off) = make_float4(0.f, 0.f, 0.f, 0.f);
            }
            asm volatile("cp.async.commit_group;" ::: "memory");
        }
        for (int dc = 0; dc < 16; dc++) {
            if (dc < 15) {
                const int b = (dc + 1) & 1;
#pragma unroll
                for (int j = 0; j < 2; j++) {
                    int idx = t + j * 512, row = idx >> 3, qd = idx & 7;
                    int gn = n0 + row, off = ES_OFF + b * ES_BUF + row * ES_S + qd * 4;
                    if (gn < NN) cpa16(sbase + off * 4, e + (size_t)gn * DD + (dc + 1) * 32 + qd * 4);
                    else *(float4*)(sm + off) = make_float4(0.f, 0.f, 0.f, 0.f);
                }
                asm volatile("cp.async.commit_group;" ::: "memory");
                asm volatile("cp.async.wait_group 1;" ::: "memory");
            } else {
                asm volatile("cp.async.wait_group 0;" ::: "memory");
            }
            __syncthreads();
            const float* Es = sm + ES_OFF + (dc & 1) * ES_BUF;
            float pc[4] = {0.f, 0.f, 0.f, 0.f};
#pragma unroll
            for (int s = 0; s < 16; s++) {
                uint32_t A[4], B[2];
                const int k0 = (s * 8 + lr) * PB_S + mt * 16 + lq;
                const int k1 = (s * 8 + 4 + lr) * PB_S + mt * 16 + lq;
                A[0] = __float_as_uint(Pb[k0]);
                A[1] = __float_as_uint(Pb[k0 + 8]);
                A[2] = __float_as_uint(Pb[k1]);
                A[3] = __float_as_uint(Pb[k1 + 8]);
                B[0] = __float_as_uint(Es[(s * 8 + lr) * ES_S + nt2 * 8 + lq]);
                B[1] = __float_as_uint(Es[(s * 8 + 4 + lr) * ES_S + nt2 * 8 + lq]);
                mma8(pc, A, B);
            }
            const int col = dc * 32 + nt2 * 8 + 2 * lr;
            float2* q0 = (float2*)(pa + (mt * 16 + lq) * PA_S + col);
            float2* q1 = (float2*)(pa + (mt * 16 + 8 + lq) * PA_S + col);
            float2 v0 = *q0, v1 = *q1;
            *q0 = make_float2(v0.x + pc[0], v0.y + pc[1]);
            *q1 = make_float2(v1.x + pc[2], v1.y + pc[3]);
            __syncthreads();
        }
    }
    // write pool partials
#pragma unroll
    for (int j = 0; j < 64; j++) {
        int idx = t + j * 512;
        g_part2[(size_t)blockIdx.x * (KK * DD) + idx] = pa[(idx >> 9) * PA_S + (idx & 511)];
    }
    // reduce head sums
#pragma unroll
    for (int off = 4; off <= 16; off <<= 1)
#pragma unroll
        for (int nt = 0; nt < 4; nt++) {
            sumacc[nt][0] += __shfl_xor_sync(0xffffffffu, sumacc[nt][0], off);
            sumacc[nt][1] += __shfl_xor_sync(0xffffffffu, sumacc[nt][1], off);
        }
    if (lane < 4)
#pragma unroll
        for (int nt = 0; nt < 4; nt++) {
            sums[w][nt * 8 + 2 * lane] = sumacc[nt][0];
            sums[w][nt * 8 + 2 * lane + 1] = sumacc[nt][1];
        }
    __syncthreads();
    if (t < KK) {
        const int h2 = t >> 5, hl = t & 31;
        float s = 0.f;
#pragma unroll
        for (int ww = 0; ww < 8; ww++) s += sums[h2 * 8 + ww][hl];
        g_sumpart[blockIdx.x * 64 + t] = s;
    }
}

// ---- K2: reduce 148 partials (fixed order) ----
__global__ __launch_bounds__(512) void pool_reduce_kernel() {
    const int k = blockIdx.x, d = threadIdx.x;
    float s = 0.f;
    for (int c = 0; c < SGRID; c++)
        s += g_part2[(size_t)c * (KK * DD) + k * DD + d];
    g_pooled[k * DD + d] = s;
}

// ---- K3: final ----
__global__ __launch_bounds__(256) void final_kernel(const float* __restrict__ Wv,
        const float* __restrict__ bv, const float* __restrict__ mu_w,
        const float* __restrict__ mu_b, const float* __restrict__ sigma_w,
        const float* __restrict__ sigma_b, float* __restrict__ out) {
    const int k = blockIdx.x, t = threadIdx.x;
    __shared__ float red[256]; __shared__ float ps[DD];
    float s = 0.f;
    for (int b = t; b < SGRID; b += 256) s += g_sumpart[b * 64 + k];
    red[t] = s;
    __syncthreads();
    for (int o = 128; o > 0; o >>= 1) { if (t < o) red[t] += red[t + o]; __syncthreads(); }
    float inv = 1.f / red[0];
    for (int d = t; d < DD; d += 256) ps[d] = g_pooled[k * DD + d] * inv;
    __syncthreads();
    const float* wr = Wv + (size_t)k * HH * DD + (size_t)t * DD;
    float acc = 0.f;
    for (int d = 0; d < DD; d += 4) {
        float4 wv = *(const float4*)(wr + d);
        acc += ps[d] * wv.x + ps[d+1] * wv.y + ps[d+2] * wv.z + ps[d+3] * wv.w;
    }
    float h = acc + bv[k * HH + t];
    float m = h * mu_w[t], g = h * sigma_w[t];
    __syncthreads();
    red[t] = m; __syncthreads();
    for (int o = 128; o > 0; o >>= 1) { if (t < o) red[t] += red[t + o]; __syncthreads(); }
    float mu = red[0] + mu_b[0];
    __syncthreads();
    red[t] = g; __syncthreads();
    for (int o = 128; o > 0; o >>= 1) { if (t < o) red[t] += red[t + o]; __syncthreads(); }
    if (t == 0) { out[k] = mu; out[KK + k] = expf(red[0] + sigma_b[0]); }
}

extern "C" void kernel_launch(void* const* d_in, const int* in_sizes, int n_in,
                              void* d_out, int out_size) {
    const float* e       = (const float*)d_in[0];
    const float* q       = (const float*)d_in[1];
    const float* Wk      = (const float*)d_in[2];
    const float* bk      = (const float*)d_in[3];
    const float* Wv      = (const float*)d_in[4];
    const float* bv      = (const float*)d_in[5];
    const float* mu_w    = (const float*)d_in[6];
    const float* mu_b    = (const float*)d_in[7];
    const float* sigma_w = (const float*)d_in[8];
    const float* sigma_b = (const float*)d_in[9];
    float* out = (float*)d_out;

    cudaFuncSetAttribute(fused_kernel, cudaFuncAttributeMaxDynamicSharedMemorySize, FS_SMEM);
    prep_kernel<<<KK, 512>>>(q, Wk, bk);
    fused_kernel<<<SGRID, 512, FS_SMEM>>>(e);
    pool_reduce_kernel<<<KK, 512>>>();
    final_kernel<<<KK, 256>>>(Wv, bv, mu_w, mu_b, sigma_w, sigma_b, out);
}

// round 15
// speedup vs baseline: 1.9502x; 1.9502x over previous
#include <cuda_runtime.h>
#include <math.h>
#include <stdint.h>

// N=200000, D=512, H=256, K=64.
// prep -> score (mma tf32, 2 CTA/SM, fused sums) -> pool (mma tf32) -> reduce -> final.
#define NN 200000
#define DD 512
#define KK 64
#define HH 256
#define SCALE 0.0625f
#define NT 1563             // ceil(200000/128) score tiles
#define SGRID 296
#define PSL_CH 43
#define PSL 1376

__device__ __align__(256) float g_qWk[KK * DD];     // [k][d]
__device__ __align__(256) float g_qbk[KK];
__device__ __align__(256) float g_sumpart[SGRID * KK];
__device__ __align__(256) float g_P[(size_t)NN * KK];        // [n][k]
__device__ __align__(256) float g_part2[(size_t)296 * KK * 256];
__device__ __align__(256) float g_pooled[KK * DD];

__device__ __forceinline__ void mma8(float* c, const uint32_t* a, const uint32_t* b) {
    asm volatile(
        "mma.sync.aligned.m16n8k8.row.col.f32.tf32.tf32.f32 "
        "{%0,%1,%2,%3}, {%4,%5,%6,%7}, {%8,%9}, {%0,%1,%2,%3};"
        : "+f"(c[0]), "+f"(c[1]), "+f"(c[2]), "+f"(c[3])
        : "r"(a[0]), "r"(a[1]), "r"(a[2]), "r"(a[3]), "r"(b[0]), "r"(b[1]));
}
__device__ __forceinline__ void cpa16(uint32_t dst, const void* src) {
    asm volatile("cp.async.cg.shared.global [%0], [%1], 16;" :: "r"(dst), "l"(src));
}
__device__ __forceinline__ uint32_t smem_u32(const void* p) {
    uint32_t a; asm("{ .reg .u64 t; cvta.to.shared.u64 t, %1; cvt.u32.u64 %0, t; }" : "=r"(a) : "l"(p)); return a;
}

// ---- K0: prep ----
__global__ __launch_bounds__(512) void prep_kernel(const float* __restrict__ q,
                                                   const float* __restrict__ Wk,
                                                   const float* __restrict__ bk) {
    const int k = blockIdx.x, t = threadIdx.x;
    __shared__ float qs[HH]; __shared__ float red[256];
    if (t < HH) qs[t] = q[k * HH + t];
    __syncthreads();
    const float* w = Wk + (size_t)k * HH * DD + t;
    float acc = 0.f;
#pragma unroll 8
    for (int h = 0; h < HH; h++) acc += qs[h] * w[(size_t)h * DD];
    g_qWk[k * DD + t] = acc;
    if (t < HH) red[t] = qs[t] * bk[k * HH + t];
    __syncthreads();
    for (int o = 128; o > 0; o >>= 1) { if (t < o) red[t] += red[t + o]; __syncthreads(); }
    if (t == 0) g_qbk[k] = red[0];
}

// ---- K1: score GEMM + exp + fused per-head sums. 256 thr, 2 CTA/SM ----
// dyn smem floats: Es x2 [128][36]=4608 each | QS x2 [64][36]=2304 each
// total 13824 fl = 55296 B
#define ES_S 36
#define ES_BUF 4608
#define QS_OFF 9216
#define QS_S 36
#define QS_BUF 2304
#define SC_SMEM 55296
__global__ __launch_bounds__(256, 2) void score_kernel(const float* __restrict__ e) {
    extern __shared__ float sm[];
    const uint32_t sbase = smem_u32(sm);
    __shared__ float sbk[KK];
    __shared__ float sums[8][KK];
    const int t = threadIdx.x, w = t >> 5, lane = t & 31;
    const int lq = lane >> 2, lr = lane & 3;
    if (t < KK) sbk[t] = g_qbk[t] * SCALE;
    __syncthreads();

    float sumacc[8][2];
#pragma unroll
    for (int nt = 0; nt < 8; nt++) { sumacc[nt][0] = 0.f; sumacc[nt][1] = 0.f; }

    for (int tile = blockIdx.x; tile < NT; tile += SGRID) {
        const int n0 = tile * 128;
        // stage chunk 0 -> buf 0
        {
#pragma unroll
            for (int j = 0; j < 4; j++) {
                int idx = t + j * 256, row = idx >> 3, qd = idx & 7;
                int gn = n0 + row, off = row * ES_S + qd * 4;
                if (gn < NN) cpa16(sbase + off * 4, e + (size_t)gn * DD + qd * 4);
                else *(float4*)(sm + off) = make_float4(0.f, 0.f, 0.f, 0.f);
            }
#pragma unroll
            for (int j = 0; j < 2; j++) {
                int idx = t + j * 256, head = idx >> 3, qd = idx & 7;
                int off = QS_OFF + head * QS_S + qd * 4;
                cpa16(sbase + off * 4, g_qWk + head * DD + qd * 4);
            }
            asm volatile("cp.async.commit_group;" ::: "memory");
        }

        float acc[8][4];
#pragma unroll
        for (int nt = 0; nt < 8; nt++)
#pragma unroll
            for (int i = 0; i < 4; i++) acc[nt][i] = 0.f;

        for (int c = 0; c < 16; c++) {
            if (c < 15) {
                const int b = (c + 1) & 1;
#pragma unroll
                for (int j = 0; j < 4; j++) {
                    int idx = t + j * 256, row = idx >> 3, qd = idx & 7;
                    int gn = n0 + row, off = b * ES_BUF + row * ES_S + qd * 4;
                    if (gn < NN) cpa16(sbase + off * 4, e + (size_t)gn * DD + (c + 1) * 32 + qd * 4);
                    else *(float4*)(sm + off) = make_float4(0.f, 0.f, 0.f, 0.f);
                }
#pragma unroll
                for (int j = 0; j < 2; j++) {
                    int idx = t + j * 256, head = idx >> 3, qd = idx & 7;
                    int off = QS_OFF + b * QS_BUF + head * QS_S + qd * 4;
                    cpa16(sbase + off * 4, g_qWk + head * DD + (c + 1) * 32 + qd * 4);
                }
                asm volatile("cp.async.commit_group;" ::: "memory");
                asm volatile("cp.async.wait_group 1;" ::: "memory");
            } else {
                asm volatile("cp.async.wait_group 0;" ::: "memory");
            }
            __syncthreads();
            const float* Es = sm + (c & 1) * ES_BUF;
            const float* Qs = sm + QS_OFF + (c & 1) * QS_BUF;
#pragma unroll
            for (int s = 0; s < 4; s++) {
                uint32_t A[4], B[8][2];
                const int ar = (w * 16 + lq) * ES_S + s * 8 + lr;
                A[0] = __float_as_uint(Es[ar]);
                A[1] = __float_as_uint(Es[ar + 8 * ES_S]);
                A[2] = __float_as_uint(Es[ar + 4]);
                A[3] = __float_as_uint(Es[ar + 8 * ES_S + 4]);
#pragma unroll
                for (int nt = 0; nt < 8; nt++) {
                    int hrow = (nt * 8 + lq) * QS_S + s * 8 + lr;
                    B[nt][0] = __float_as_uint(Qs[hrow]);
                    B[nt][1] = __float_as_uint(Qs[hrow + 4]);
                }
#pragma unroll
                for (int nt = 0; nt < 8; nt++) mma8(acc[nt], A, B[nt]);
            }
            __syncthreads();
        }
        // epilogue: exp + store P + accumulate head sums
        const int r0 = n0 + w * 16 + lq, r1 = r0 + 8;
        const bool ok0 = r0 < NN, ok1 = r1 < NN;
#pragma unroll
        for (int nt = 0; nt < 8; nt++) {
            const int h = nt * 8 + 2 * lr;
            const float b0 = sbk[h], b1 = sbk[h + 1];
            if (ok0) {
                float p0 = __expf(acc[nt][0] * SCALE + b0);
                float p1 = __expf(acc[nt][1] * SCALE + b1);
                *(float2*)(g_P + (size_t)r0 * 64 + h) = make_float2(p0, p1);
                sumacc[nt][0] += p0; sumacc[nt][1] += p1;
            }
            if (ok1) {
                float p0 = __expf(acc[nt][2] * SCALE + b0);
                float p1 = __expf(acc[nt][3] * SCALE + b1);
                *(float2*)(g_P + (size_t)r1 * 64 + h) = make_float2(p0, p1);
                sumacc[nt][0] += p0; sumacc[nt][1] += p1;
            }
        }
    }
    // reduce sums over lq lanes
#pragma unroll
    for (int off = 4; off <= 16; off <<= 1)
#pragma unroll
        for (int nt = 0; nt < 8; nt++) {
            sumacc[nt][0] += __shfl_xor_sync(0xffffffffu, sumacc[nt][0], off);
            sumacc[nt][1] += __shfl_xor_sync(0xffffffffu, sumacc[nt][1], off);
        }
    if (lane < 4)
#pragma unroll
        for (int nt = 0; nt < 8; nt++) {
            sums[w][nt * 8 + 2 * lane] = sumacc[nt][0];
            sums[w][nt * 8 + 2 * lane + 1] = sumacc[nt][1];
        }
    __syncthreads();
    if (t < KK) {
        float s = 0.f;
#pragma unroll
        for (int ww = 0; ww < 8; ww++) s += sums[ww][t];
        g_sumpart[blockIdx.x * 64 + t] = s;
    }
}

// ---- K2: pool GEMM via mma tf32 (R8, proven) ----
#define PM_SMEM 86016
__global__ __launch_bounds__(256) void poolmma_kernel(const float* __restrict__ e) {
    extern __shared__ float sm2[];
    float* PsB[2] = {sm2, sm2 + 2304};
    float* EsB[2] = {sm2 + 4608, sm2 + 13056};
    const uint32_t sbase = smem_u32(sm2);
    const int t = threadIdx.x, w = t >> 5, lane = t & 31;
    const int lq = lane >> 2, lr = lane & 3;
    const int dhalf = blockIdx.x & 1, slice = blockIdx.x >> 1;
    const int nbeg = slice * PSL;
    int nch = 0;
    if (nbeg < NN) { int r = (NN - nbeg + 31) / 32; nch = r < PSL_CH ? r : PSL_CH; }

    float acc[4][4][4];
#pragma unroll
    for (int mt = 0; mt < 4; mt++)
#pragma unroll
        for (int nt = 0; nt < 4; nt++)
#pragma unroll
            for (int i = 0; i < 4; i++) acc[mt][nt][i] = 0.f;

    if (nch > 0) {
#pragma unroll
        for (int j = 0; j < 8; j++) {
            int idx = t + j * 256, row = idx >> 6, c4 = idx & 63;
            int gn = nbeg + row;
            uint32_t dst = sbase + (4608 + row * 264 + c4 * 4) * 4;
            if (gn < NN) cpa16(dst, e + (size_t)gn * DD + dhalf * 256 + c4 * 4);
            else *(float4*)(EsB[0] + row * 264 + c4 * 4) = make_float4(0.f, 0.f, 0.f, 0.f);
        }
#pragma unroll
        for (int j = 0; j < 2; j++) {
            int idx = t + j * 256, row = idx >> 4, c4 = idx & 15;
            int gn = nbeg + row;
            uint32_t dst = sbase + (row * 72 + c4 * 4) * 4;
            if (gn < NN) cpa16(dst, g_P + (size_t)gn * 64 + c4 * 4);
            else *(float4*)(PsB[0] + row * 72 + c4 * 4) = make_float4(0.f, 0.f, 0.f, 0.f);
        }
        asm volatile("cp.async.commit_group;" ::: "memory");

        for (int c = 0; c < nch; c++) {
            const int b = c & 1;
            if (c + 1 < nch) {
                const int nb2 = (c + 1) & 1;
                const int n1 = nbeg + (c + 1) * 32;
#pragma unroll
                for (int j = 0; j < 8; j++) {
                    int idx = t + j * 256, row = idx >> 6, c4 = idx & 63;
                    int gn = n1 + row;
                    uint32_t dst = sbase + ((4608 + nb2 * 8448) + row * 264 + c4 * 4) * 4;
                    if (gn < NN) cpa16(dst, e + (size_t)gn * DD + dhalf * 256 + c4 * 4);
                    else *(float4*)(EsB[nb2] + row * 264 + c4 * 4) = make_float4(0.f, 0.f, 0.f, 0.f);
                }
#pragma unroll
                for (int j = 0; j < 2; j++) {
                    int idx = t + j * 256, row = idx >> 4, c4 = idx & 15;
                    int gn = n1 + row;
                    uint32_t dst = sbase + ((nb2 * 2304) + row * 72 + c4 * 4) * 4;
                    if (gn < NN) cpa16(dst, g_P + (size_t)gn * 64 + c4 * 4);
                    else *(float4*)(PsB[nb2] + row * 72 + c4 * 4) = make_float4(0.f, 0.f, 0.f, 0.f);
                }
                asm volatile("cp.async.commit_group;" ::: "memory");
                asm volatile("cp.async.wait_group 1;" ::: "memory");
            } else {
                asm volatile("cp.async.wait_group 0;" ::: "memory");
            }
            __syncthreads();
            const float* Ps = PsB[b];
            const float* Es = EsB[b];
#pragma unroll
            for (int s = 0; s < 4; s++) {
                uint32_t A[4][4], B[4][2];
#pragma unroll
                for (int mt = 0; mt < 4; mt++) {
                    A[mt][0] = __float_as_uint(Ps[(s * 8 + lr) * 72 + mt * 16 + lq]);
                    A[mt][1] = __float_as_uint(Ps[(s * 8 + lr) * 72 + mt * 16 + 8 + lq]);
                    A[mt][2] = __float_as_uint(Ps[(s * 8 + 4 + lr) * 72 + mt * 16 + lq]);
                    A[mt][3] = __float_as_uint(Ps[(s * 8 + 4 + lr) * 72 + mt * 16 + 8 + lq]);
                }
#pragma unroll
                for (int nt = 0; nt < 4; nt++) {
                    int dcol = w * 32 + nt * 8 + lq;
                    B[nt][0] = __float_as_uint(Es[(s * 8 + lr) * 264 + dcol]);
                    B[nt][1] = __float_as_uint(Es[(s * 8 + 4 + lr) * 264 + dcol]);
                }
#pragma unroll
                for (int mt = 0; mt < 4; mt++)
#pragma unroll
                    for (int nt = 0; nt < 4; nt++) mma8(acc[mt][nt], A[mt], B[nt]);
            }
            __syncthreads();
        }
    }
    float* dst = g_part2 + (size_t)blockIdx.x * (64 * 256);
#pragma unroll
    for (int mt = 0; mt < 4; mt++)
#pragma unroll
        for (int nt = 0; nt < 4; nt++) {
            int head = mt * 16 + lq, d = w * 32 + nt * 8 + 2 * lr;
            *(float2*)(dst + head * 256 + d)       = make_float2(acc[mt][nt][0], acc[mt][nt][1]);
            *(float2*)(dst + (head + 8) * 256 + d) = make_float2(acc[mt][nt][2], acc[mt][nt][3]);
        }
}

// ---- K3: reduce ----
__global__ __launch_bounds__(512) void pool_reduce_kernel() {
    const int k = blockIdx.x, d = threadIdx.x;
    const int dhalf = d >> 8, dl = d & 255;
    float s = 0.f;
    for (int sl = 0; sl < 148; sl++)
        s += g_part2[(size_t)(sl * 2 + dhalf) * (64 * 256) + k * 256 + dl];
    g_pooled[k * DD + d] = s;
}

// ---- K4: final ----
__global__ __launch_bounds__(256) void final_kernel(const float* __restrict__ Wv,
        const float* __restrict__ bv, const float* __restrict__ mu_w,
        const float* __restrict__ mu_b, const float* __restrict__ sigma_w,
        const float* __restrict__ sigma_b, float* __restrict__ out) {
    const int k = blockIdx.x, t = threadIdx.x;
    __shared__ float red[256]; __shared__ float ps[DD];
    float s = 0.f;
    for (int b = t; b < SGRID; b += 256) s += g_sumpart[b * 64 + k];
    red[t] = s;
    __syncthreads();
    for (int o = 128; o > 0; o >>= 1) { if (t < o) red[t] += red[t + o]; __syncthreads(); }
    float inv = 1.f / red[0];
    for (int d = t; d < DD; d += 256) ps[d] = g_pooled[k * DD + d] * inv;
    __syncthreads();
    const float* wr = Wv + (size_t)k * HH * DD + (size_t)t * DD;
    float acc = 0.f;
    for (int d = 0; d < DD; d += 4) {
        float4 wv = *(const float4*)(wr + d);
        acc += ps[d] * wv.x + ps[d+1] * wv.y + ps[d+2] * wv.z + ps[d+3] * wv.w;
    }
    float h = acc + bv[k * HH + t];
    float m = h * mu_w[t], g = h * sigma_w[t];
    __syncthreads();
    red[t] = m; __syncthreads();
    for (int o = 128; o > 0; o >>= 1) { if (t < o) red[t] += red[t + o]; __syncthreads(); }
    float mu = red[0] + mu_b[0];
    __syncthreads();
    red[t] = g; __syncthreads();
    for (int o = 128; o > 0; o >>= 1) { if (t < o) red[t] += red[t + o]; __syncthreads(); }
    if (t == 0) { out[k] = mu; out[KK + k] = expf(red[0] + sigma_b[0]); }
}

extern "C" void kernel_launch(void* const* d_in, const int* in_sizes, int n_in,
                              void* d_out, int out_size) {
    const float* e       = (const float*)d_in[0];
    const float* q       = (const float*)d_in[1];
    const float* Wk      = (const float*)d_in[2];
    const float* bk      = (const float*)d_in[3];
    const float* Wv      = (const float*)d_in[4];
    const float* bv      = (const float*)d_in[5];
    const float* mu_w    = (const float*)d_in[6];
    const float* mu_b    = (const float*)d_in[7];
    const float* sigma_w = (const float*)d_in[8];
    const float* sigma_b = (const float*)d_in[9];
    float* out = (float*)d_out;

    cudaFuncSetAttribute(score_kernel, cudaFuncAttributeMaxDynamicSharedMemorySize, SC_SMEM);
    cudaFuncSetAttribute(poolmma_kernel, cudaFuncAttributeMaxDynamicSharedMemorySize, PM_SMEM);
    prep_kernel<<<KK, 512>>>(q, Wk, bk);
    score_kernel<<<SGRID, 256, SC_SMEM>>>(e);
    poolmma_kernel<<<296, 256, PM_SMEM>>>(e);
    pool_reduce_kernel<<<KK, 512>>>();
    final_kernel<<<KK, 256>>>(Wv, bv, mu_w, mu_b, sigma_w, sigma_b, out);
}

// round 16
// speedup vs baseline: 1.9813x; 1.0159x over previous
#include <cuda_runtime.h>
#include <math.h>
#include <stdint.h>

// N=200000, D=512, H=256, K=64.
// prep -> score (mma tf32, 64-d chunks, 2 CTA/SM, fused sums) -> pool (mma tf32)
// -> reduce -> final (coalesced Wv).
#define NN 200000
#define DD 512
#define KK 64
#define HH 256
#define SCALE 0.0625f
#define NT 1563
#define SGRID 296
#define PSL_CH 43
#define PSL 1376

__device__ __align__(256) float g_qWk[KK * DD];     // [k][d]
__device__ __align__(256) float g_qbk[KK];
__device__ __align__(256) float g_sumpart[SGRID * KK];
__device__ __align__(256) float g_P[(size_t)NN * KK];        // [n][k]
__device__ __align__(256) float g_part2[(size_t)296 * KK * 256];
__device__ __align__(256) float g_pooled[KK * DD];

__device__ __forceinline__ void mma8(float* c, const uint32_t* a, const uint32_t* b) {
    asm volatile(
        "mma.sync.aligned.m16n8k8.row.col.f32.tf32.tf32.f32 "
        "{%0,%1,%2,%3}, {%4,%5,%6,%7}, {%8,%9}, {%0,%1,%2,%3};"
        : "+f"(c[0]), "+f"(c[1]), "+f"(c[2]), "+f"(c[3])
        : "r"(a[0]), "r"(a[1]), "r"(a[2]), "r"(a[3]), "r"(b[0]), "r"(b[1]));
}
__device__ __forceinline__ void cpa16(uint32_t dst, const void* src) {
    asm volatile("cp.async.cg.shared.global [%0], [%1], 16;" :: "r"(dst), "l"(src));
}
__device__ __forceinline__ uint32_t smem_u32(const void* p) {
    uint32_t a; asm("{ .reg .u64 t; cvta.to.shared.u64 t, %1; cvt.u32.u64 %0, t; }" : "=r"(a) : "l"(p)); return a;
}

// ---- K0: prep ----
__global__ __launch_bounds__(512) void prep_kernel(const float* __restrict__ q,
                                                   const float* __restrict__ Wk,
                                                   const float* __restrict__ bk) {
    const int k = blockIdx.x, t = threadIdx.x;
    __shared__ float qs[HH]; __shared__ float red[256];
    if (t < HH) qs[t] = q[k * HH + t];
    __syncthreads();
    const float* w = Wk + (size_t)k * HH * DD + t;
    float acc = 0.f;
#pragma unroll 8
    for (int h = 0; h < HH; h++) acc += qs[h] * w[(size_t)h * DD];
    g_qWk[k * DD + t] = acc;
    if (t < HH) red[t] = qs[t] * bk[k * HH + t];
    __syncthreads();
    for (int o = 128; o > 0; o >>= 1) { if (t < o) red[t] += red[t + o]; __syncthreads(); }
    if (t == 0) g_qbk[k] = red[0];
}

// ---- K1: score GEMM + exp + fused per-head sums. 64-d chunks, 2 CTA/SM ----
// dyn smem floats: Es x2 [128][68]=8704 each | QS x2 [64][68]=4352 each
// total 26112 fl = 104448 B
#define ES_S 68
#define ES_BUF 8704
#define QS_OFF 17408
#define QS_S 68
#define QS_BUF 4352
#define SC_SMEM 104448
__global__ __launch_bounds__(256, 2) void score_kernel(const float* __restrict__ e) {
    extern __shared__ float sm[];
    const uint32_t sbase = smem_u32(sm);
    __shared__ float sbk[KK];
    __shared__ float sums[8][KK];
    const int t = threadIdx.x, w = t >> 5, lane = t & 31;
    const int lq = lane >> 2, lr = lane & 3;
    if (t < KK) sbk[t] = g_qbk[t] * SCALE;
    __syncthreads();

    float sumacc[8][2];
#pragma unroll
    for (int nt = 0; nt < 8; nt++) { sumacc[nt][0] = 0.f; sumacc[nt][1] = 0.f; }

    for (int tile = blockIdx.x; tile < NT; tile += SGRID) {
        const int n0 = tile * 128;
        // stage chunk 0 -> buf 0
        {
#pragma unroll
            for (int j = 0; j < 8; j++) {
                int idx = t + j * 256, row = idx >> 4, qd = idx & 15;
                int gn = n0 + row, off = row * ES_S + qd * 4;
                if (gn < NN) cpa16(sbase + off * 4, e + (size_t)gn * DD + qd * 4);
                else *(float4*)(sm + off) = make_float4(0.f, 0.f, 0.f, 0.f);
            }
#pragma unroll
            for (int j = 0; j < 4; j++) {
                int idx = t + j * 256, head = idx >> 4, qd = idx & 15;
                int off = QS_OFF + head * QS_S + qd * 4;
                cpa16(sbase + off * 4, g_qWk + head * DD + qd * 4);
            }
            asm volatile("cp.async.commit_group;" ::: "memory");
        }

        float acc[8][4];
#pragma unroll
        for (int nt = 0; nt < 8; nt++)
#pragma unroll
            for (int i = 0; i < 4; i++) acc[nt][i] = 0.f;

        for (int c = 0; c < 8; c++) {
            if (c < 7) {
                const int b = (c + 1) & 1;
#pragma unroll
                for (int j = 0; j < 8; j++) {
                    int idx = t + j * 256, row = idx >> 4, qd = idx & 15;
                    int gn = n0 + row, off = b * ES_BUF + row * ES_S + qd * 4;
                    if (gn < NN) cpa16(sbase + off * 4, e + (size_t)gn * DD + (c + 1) * 64 + qd * 4);
                    else *(float4*)(sm + off) = make_float4(0.f, 0.f, 0.f, 0.f);
                }
#pragma unroll
                for (int j = 0; j < 4; j++) {
                    int idx = t + j * 256, head = idx >> 4, qd = idx & 15;
                    int off = QS_OFF + b * QS_BUF + head * QS_S + qd * 4;
                    cpa16(sbase + off * 4, g_qWk + head * DD + (c + 1) * 64 + qd * 4);
                }
                asm volatile("cp.async.commit_group;" ::: "memory");
                asm volatile("cp.async.wait_group 1;" ::: "memory");
            } else {
                asm volatile("cp.async.wait_group 0;" ::: "memory");
            }
            __syncthreads();
            const float* Es = sm + (c & 1) * ES_BUF;
            const float* Qs = sm + QS_OFF + (c & 1) * QS_BUF;
#pragma unroll
            for (int s = 0; s < 8; s++) {
                uint32_t A[4], B[8][2];
                const int ar = (w * 16 + lq) * ES_S + s * 8 + lr;
                A[0] = __float_as_uint(Es[ar]);
                A[1] = __float_as_uint(Es[ar + 8 * ES_S]);
                A[2] = __float_as_uint(Es[ar + 4]);
                A[3] = __float_as_uint(Es[ar + 8 * ES_S + 4]);
#pragma unroll
                for (int nt = 0; nt < 8; nt++) {
                    int hrow = (nt * 8 + lq) * QS_S + s * 8 + lr;
                    B[nt][0] = __float_as_uint(Qs[hrow]);
                    B[nt][1] = __float_as_uint(Qs[hrow + 4]);
                }
#pragma unroll
                for (int nt = 0; nt < 8; nt++) mma8(acc[nt], A, B[nt]);
            }
            __syncthreads();
        }
        // epilogue: exp + store P + accumulate head sums
        const int r0 = n0 + w * 16 + lq, r1 = r0 + 8;
        const bool ok0 = r0 < NN, ok1 = r1 < NN;
#pragma unroll
        for (int nt = 0; nt < 8; nt++) {
            const int h = nt * 8 + 2 * lr;
            const float b0 = sbk[h], b1 = sbk[h + 1];
            if (ok0) {
                float p0 = __expf(acc[nt][0] * SCALE + b0);
                float p1 = __expf(acc[nt][1] * SCALE + b1);
                *(float2*)(g_P + (size_t)r0 * 64 + h) = make_float2(p0, p1);
                sumacc[nt][0] += p0; sumacc[nt][1] += p1;
            }
            if (ok1) {
                float p0 = __expf(acc[nt][2] * SCALE + b0);
                float p1 = __expf(acc[nt][3] * SCALE + b1);
                *(float2*)(g_P + (size_t)r1 * 64 + h) = make_float2(p0, p1);
                sumacc[nt][0] += p0; sumacc[nt][1] += p1;
            }
        }
    }
#pragma unroll
    for (int off = 4; off <= 16; off <<= 1)
#pragma unroll
        for (int nt = 0; nt < 8; nt++) {
            sumacc[nt][0] += __shfl_xor_sync(0xffffffffu, sumacc[nt][0], off);
            sumacc[nt][1] += __shfl_xor_sync(0xffffffffu, sumacc[nt][1], off);
        }
    if (lane < 4)
#pragma unroll
        for (int nt = 0; nt < 8; nt++) {
            sums[w][nt * 8 + 2 * lane] = sumacc[nt][0];
            sums[w][nt * 8 + 2 * lane + 1] = sumacc[nt][1];
        }
    __syncthreads();
    if (t < KK) {
        float s = 0.f;
#pragma unroll
        for (int ww = 0; ww < 8; ww++) s += sums[ww][t];
        g_sumpart[blockIdx.x * 64 + t] = s;
    }
}

// ---- K2: pool GEMM via mma tf32 (proven) ----
#define PM_SMEM 86016
__global__ __launch_bounds__(256) void poolmma_kernel(const float* __restrict__ e) {
    extern __shared__ float sm2[];
    float* PsB[2] = {sm2, sm2 + 2304};
    float* EsB[2] = {sm2 + 4608, sm2 + 13056};
    const uint32_t sbase = smem_u32(sm2);
    const int t = threadIdx.x, w = t >> 5, lane = t & 31;
    const int lq = lane >> 2, lr = lane & 3;
    const int dhalf = blockIdx.x & 1, slice = blockIdx.x >> 1;
    const int nbeg = slice * PSL;
    int nch = 0;
    if (nbeg < NN) { int r = (NN - nbeg + 31) / 32; nch = r < PSL_CH ? r : PSL_CH; }

    float acc[4][4][4];
#pragma unroll
    for (int mt = 0; mt < 4; mt++)
#pragma unroll
        for (int nt = 0; nt < 4; nt++)
#pragma unroll
            for (int i = 0; i < 4; i++) acc[mt][nt][i] = 0.f;

    if (nch > 0) {
#pragma unroll
        for (int j = 0; j < 8; j++) {
            int idx = t + j * 256, row = idx >> 6, c4 = idx & 63;
            int gn = nbeg + row;
            uint32_t dst = sbase + (4608 + row * 264 + c4 * 4) * 4;
            if (gn < NN) cpa16(dst, e + (size_t)gn * DD + dhalf * 256 + c4 * 4);
            else *(float4*)(EsB[0] + row * 264 + c4 * 4) = make_float4(0.f, 0.f, 0.f, 0.f);
        }
#pragma unroll
        for (int j = 0; j < 2; j++) {
            int idx = t + j * 256, row = idx >> 4, c4 = idx & 15;
            int gn = nbeg + row;
            uint32_t dst = sbase + (row * 72 + c4 * 4) * 4;
            if (gn < NN) cpa16(dst, g_P + (size_t)gn * 64 + c4 * 4);
            else *(float4*)(PsB[0] + row * 72 + c4 * 4) = make_float4(0.f, 0.f, 0.f, 0.f);
        }
        asm volatile("cp.async.commit_group;" ::: "memory");

        for (int c = 0; c < nch; c++) {
            const int b = c & 1;
            if (c + 1 < nch) {
                const int nb2 = (c + 1) & 1;
                const int n1 = nbeg + (c + 1) * 32;
#pragma unroll
                for (int j = 0; j < 8; j++) {
                    int idx = t + j * 256, row = idx >> 6, c4 = idx & 63;
                    int gn = n1 + row;
                    uint32_t dst = sbase + ((4608 + nb2 * 8448) + row * 264 + c4 * 4) * 4;
                    if (gn < NN) cpa16(dst, e + (size_t)gn * DD + dhalf * 256 + c4 * 4);
                    else *(float4*)(EsB[nb2] + row * 264 + c4 * 4) = make_float4(0.f, 0.f, 0.f, 0.f);
                }
#pragma unroll
                for (int j = 0; j < 2; j++) {
                    int idx = t + j * 256, row = idx >> 4, c4 = idx & 15;
                    int gn = n1 + row;
                    uint32_t dst = sbase + ((nb2 * 2304) + row * 72 + c4 * 4) * 4;
                    if (gn < NN) cpa16(dst, g_P + (size_t)gn * 64 + c4 * 4);
                    else *(float4*)(PsB[nb2] + row * 72 + c4 * 4) = make_float4(0.f, 0.f, 0.f, 0.f);
                }
                asm volatile("cp.async.commit_group;" ::: "memory");
                asm volatile("cp.async.wait_group 1;" ::: "memory");
            } else {
                asm volatile("cp.async.wait_group 0;" ::: "memory");
            }
            __syncthreads();
            const float* Ps = PsB[b];
            const float* Es = EsB[b];
#pragma unroll
            for (int s = 0; s < 4; s++) {
                uint32_t A[4][4], B[4][2];
#pragma unroll
                for (int mt = 0; mt < 4; mt++) {
                    A[mt][0] = __float_as_uint(Ps[(s * 8 + lr) * 72 + mt * 16 + lq]);
                    A[mt][1] = __float_as_uint(Ps[(s * 8 + lr) * 72 + mt * 16 + 8 + lq]);
                    A[mt][2] = __float_as_uint(Ps[(s * 8 + 4 + lr) * 72 + mt * 16 + lq]);
                    A[mt][3] = __float_as_uint(Ps[(s * 8 + 4 + lr) * 72 + mt * 16 + 8 + lq]);
                }
#pragma unroll
                for (int nt = 0; nt < 4; nt++) {
                    int dcol = w * 32 + nt * 8 + lq;
                    B[nt][0] = __float_as_uint(Es[(s * 8 + lr) * 264 + dcol]);
                    B[nt][1] = __float_as_uint(Es[(s * 8 + 4 + lr) * 264 + dcol]);
                }
#pragma unroll
                for (int mt = 0; mt < 4; mt++)
#pragma unroll
                    for (int nt = 0; nt < 4; nt++) mma8(acc[mt][nt], A[mt], B[nt]);
            }
            __syncthreads();
        }
    }
    float* dst = g_part2 + (size_t)blockIdx.x * (64 * 256);
#pragma unroll
    for (int mt = 0; mt < 4; mt++)
#pragma unroll
        for (int nt = 0; nt < 4; nt++) {
            int head = mt * 16 + lq, d = w * 32 + nt * 8 + 2 * lr;
            *(float2*)(dst + head * 256 + d)       = make_float2(acc[mt][nt][0], acc[mt][nt][1]);
            *(float2*)(dst + (head + 8) * 256 + d) = make_float2(acc[mt][nt][2], acc[mt][nt][3]);
        }
}

// ---- K3: reduce ----
__global__ __launch_bounds__(512) void pool_reduce_kernel() {
    const int k = blockIdx.x, d = threadIdx.x;
    const int dhalf = d >> 8, dl = d & 255;
    float s = 0.f;
    for (int sl = 0; sl < 148; sl++)
        s += g_part2[(size_t)(sl * 2 + dhalf) * (64 * 256) + k * 256 + dl];
    g_pooled[k * DD + d] = s;
}

// ---- K4: final (coalesced Wv) ----
__global__ __launch_bounds__(256) void final_kernel(const float* __restrict__ Wv,
        const float* __restrict__ bv, const float* __restrict__ mu_w,
        const float* __restrict__ mu_b, const float* __restrict__ sigma_w,
        const float* __restrict__ sigma_b, float* __restrict__ out) {
    const int k = blockIdx.x, t = threadIdx.x, w = t >> 5, lane = t & 31;
    __shared__ float red[256]; __shared__ float ps[DD]; __shared__ float hm[HH];
    float s = 0.f;
    for (int b = t; b < SGRID; b += 256) s += g_sumpart[b * 64 + k];
    red[t] = s;
    __syncthreads();
    for (int o = 128; o > 0; o >>= 1) { if (t < o) red[t] += red[t + o]; __syncthreads(); }
    float inv = 1.f / red[0];
    for (int d = t; d < DD; d += 256) ps[d] = g_pooled[k * DD + d] * inv;
    __syncthreads();
    // h_multi: one warp per h-row (coalesced Wv reads), 32 rows per warp
    for (int i = 0; i < 32; i++) {
        const int h = w * 32 + i;
        const float* wr = Wv + (size_t)k * HH * DD + (size_t)h * DD;
        float a = 0.f;
#pragma unroll
        for (int j = 0; j < 4; j++) {
            const int d = lane * 4 + j * 128;
            float4 v = *(const float4*)(wr + d);
            a += ps[d] * v.x + ps[d + 1] * v.y + ps[d + 2] * v.z + ps[d + 3] * v.w;
        }
#pragma unroll
        for (int o = 16; o > 0; o >>= 1) a += __shfl_xor_sync(0xffffffffu, a, o);
        if (lane == 0) hm[h] = a + bv[k * HH + h];
    }
    __syncthreads();
    float h = hm[t];
    float m = h * mu_w[t], g = h * sigma_w[t];
    red[t] = m;
    __syncthreads();
    for (int o = 128; o > 0; o >>= 1) { if (t < o) red[t] += red[t + o]; __syncthreads(); }
    float mu = red[0] + mu_b[0];
    __syncthreads();
    red[t] = g;
    __syncthreads();
    for (int o = 128; o > 0; o >>= 1) { if (t < o) red[t] += red[t + o]; __syncthreads(); }
    if (t == 0) { out[k] = mu; out[KK + k] = expf(red[0] + sigma_b[0]); }
}

extern "C" void kernel_launch(void* const* d_in, const int* in_sizes, int n_in,
                              void* d_out, int out_size) {
    const float* e       = (const float*)d_in[0];
    const float* q       = (const float*)d_in[1];
    const float* Wk      = (const float*)d_in[2];
    const float* bk      = (const float*)d_in[3];
    const float* Wv      = (const float*)d_in[4];
    const float* bv      = (const float*)d_in[5];
    const float* mu_w    = (const float*)d_in[6];
    const float* mu_b    = (const float*)d_in[7];
    const float* sigma_w = (const float*)d_in[8];
    const float* sigma_b = (const float*)d_in[9];
    float* out = (float*)d_out;

    cudaFuncSetAttribute(score_kernel, cudaFuncAttributeMaxDynamicSharedMemorySize, SC_SMEM);
    cudaFuncSetAttribute(poolmma_kernel, cudaFuncAttributeMaxDynamicSharedMemorySize, PM_SMEM);
    prep_kernel<<<KK, 512>>>(q, Wk, bk);
    score_kernel<<<SGRID, 256, SC_SMEM>>>(e);
    poolmma_kernel<<<296, 256, PM_SMEM>>>(e);
    pool_reduce_kernel<<<KK, 512>>>();
    final_kernel<<<KK, 256>>>(Wv, bv, mu_w, mu_b, sigma_w, sigma_b, out);
}

// round 17
// speedup vs baseline: 1.9936x; 1.0062x over previous
#include <cuda_runtime.h>
#include <cuda_fp16.h>
#include <math.h>
#include <stdint.h>

// N=200000, D=512, H=256, K=64.
// prep -> score (mma tf32, P stored fp16 coalesced, fused sums)
// -> pool (mma tf32, fp16 P) -> reduce -> final.
#define NN 200000
#define DD 512
#define KK 64
#define HH 256
#define SCALE 0.0625f
#define NT 1563
#define SGRID 296
#define PSL_CH 43
#define PSL 1376

__device__ __align__(256) float g_qWk[KK * DD];
__device__ __align__(256) float g_qbk[KK];
__device__ __align__(256) float g_sumpart[SGRID * KK];
__device__ __align__(256) unsigned int g_Ph[(size_t)NN * 32];   // fp16x2 [n][32]
__device__ __align__(256) float g_part2[(size_t)296 * KK * 256];
__device__ __align__(256) float g_pooled[KK * DD];

__device__ __forceinline__ void mma8(float* c, const uint32_t* a, const uint32_t* b) {
    asm volatile(
        "mma.sync.aligned.m16n8k8.row.col.f32.tf32.tf32.f32 "
        "{%0,%1,%2,%3}, {%4,%5,%6,%7}, {%8,%9}, {%0,%1,%2,%3};"
        : "+f"(c[0]), "+f"(c[1]), "+f"(c[2]), "+f"(c[3])
        : "r"(a[0]), "r"(a[1]), "r"(a[2]), "r"(a[3]), "r"(b[0]), "r"(b[1]));
}
__device__ __forceinline__ void cpa16(uint32_t dst, const void* src) {
    asm volatile("cp.async.cg.shared.global [%0], [%1], 16;" :: "r"(dst), "l"(src));
}
__device__ __forceinline__ uint32_t smem_u32(const void* p) {
    uint32_t a; asm("{ .reg .u64 t; cvta.to.shared.u64 t, %1; cvt.u32.u64 %0, t; }" : "=r"(a) : "l"(p)); return a;
}
__device__ __forceinline__ uint32_t pkh2(float lo, float hi) {
    __half2 hv = __floats2half2_rn(lo, hi);
    return *reinterpret_cast<uint32_t*>(&hv);
}
__device__ __forceinline__ uint32_t h2f(uint32_t w, int hi) {
    __half2 hv = *reinterpret_cast<const __half2*>(&w);
    float2 f = __half22float2(hv);
    return __float_as_uint(hi ? f.y : f.x);
}

// ---- K0: prep ----
__global__ __launch_bounds__(512) void prep_kernel(const float* __restrict__ q,
                                                   const float* __restrict__ Wk,
                                                   const float* __restrict__ bk) {
    const int k = blockIdx.x, t = threadIdx.x;
    __shared__ float qs[HH]; __shared__ float red[256];
    if (t < HH) qs[t] = q[k * HH + t];
    __syncthreads();
    const float* w = Wk + (size_t)k * HH * DD + t;
    float acc = 0.f;
#pragma unroll 8
    for (int h = 0; h < HH; h++) acc += qs[h] * w[(size_t)h * DD];
    g_qWk[k * DD + t] = acc;
    if (t < HH) red[t] = qs[t] * bk[k * HH + t];
    __syncthreads();
    for (int o = 128; o > 0; o >>= 1) { if (t < o) red[t] += red[t + o]; __syncthreads(); }
    if (t == 0) g_qbk[k] = red[0];
}

// ---- K1: score GEMM + exp + fp16 P + fused sums. 64-d chunks, 2 CTA/SM ----
#define ES_S 68
#define ES_BUF 8704
#define QS_OFF 17408
#define QS_S 68
#define QS_BUF 4352
#define SC_SMEM 104448
__global__ __launch_bounds__(256, 2) void score_kernel(const float* __restrict__ e) {
    extern __shared__ float sm[];
    const uint32_t sbase = smem_u32(sm);
    __shared__ float sbk[KK];
    __shared__ float sums[8][KK];
    const int t = threadIdx.x, w = t >> 5, lane = t & 31;
    const int lq = lane >> 2, lr = lane & 3;
    if (t < KK) sbk[t] = g_qbk[t] * SCALE;
    __syncthreads();

    float sumacc[8][2];
#pragma unroll
    for (int nt = 0; nt < 8; nt++) { sumacc[nt][0] = 0.f; sumacc[nt][1] = 0.f; }

    for (int tile = blockIdx.x; tile < NT; tile += SGRID) {
        const int n0 = tile * 128;
        {
#pragma unroll
            for (int j = 0; j < 8; j++) {
                int idx = t + j * 256, row = idx >> 4, qd = idx & 15;
                int gn = n0 + row, off = row * ES_S + qd * 4;
                if (gn < NN) cpa16(sbase + off * 4, e + (size_t)gn * DD + qd * 4);
                else *(float4*)(sm + off) = make_float4(0.f, 0.f, 0.f, 0.f);
            }
#pragma unroll
            for (int j = 0; j < 4; j++) {
                int idx = t + j * 256, head = idx >> 4, qd = idx & 15;
                int off = QS_OFF + head * QS_S + qd * 4;
                cpa16(sbase + off * 4, g_qWk + head * DD + qd * 4);
            }
            asm volatile("cp.async.commit_group;" ::: "memory");
        }

        float acc[8][4];
#pragma unroll
        for (int nt = 0; nt < 8; nt++)
#pragma unroll
            for (int i = 0; i < 4; i++) acc[nt][i] = 0.f;

        for (int c = 0; c < 8; c++) {
            if (c < 7) {
                const int b = (c + 1) & 1;
#pragma unroll
                for (int j = 0; j < 8; j++) {
                    int idx = t + j * 256, row = idx >> 4, qd = idx & 15;
                    int gn = n0 + row, off = b * ES_BUF + row * ES_S + qd * 4;
                    if (gn < NN) cpa16(sbase + off * 4, e + (size_t)gn * DD + (c + 1) * 64 + qd * 4);
                    else *(float4*)(sm + off) = make_float4(0.f, 0.f, 0.f, 0.f);
                }
#pragma unroll
                for (int j = 0; j < 4; j++) {
                    int idx = t + j * 256, head = idx >> 4, qd = idx & 15;
                    int off = QS_OFF + b * QS_BUF + head * QS_S + qd * 4;
                    cpa16(sbase + off * 4, g_qWk + head * DD + (c + 1) * 64 + qd * 4);
                }
                asm volatile("cp.async.commit_group;" ::: "memory");
                asm volatile("cp.async.wait_group 1;" ::: "memory");
            } else {
                asm volatile("cp.async.wait_group 0;" ::: "memory");
            }
            __syncthreads();
            const float* Es = sm + (c & 1) * ES_BUF;
            const float* Qs = sm + QS_OFF + (c & 1) * QS_BUF;
#pragma unroll
            for (int s = 0; s < 8; s++) {
                uint32_t A[4], B[8][2];
                const int ar = (w * 16 + lq) * ES_S + s * 8 + lr;
                A[0] = __float_as_uint(Es[ar]);
                A[1] = __float_as_uint(Es[ar + 8 * ES_S]);
                A[2] = __float_as_uint(Es[ar + 4]);
                A[3] = __float_as_uint(Es[ar + 8 * ES_S + 4]);
#pragma unroll
                for (int nt = 0; nt < 8; nt++) {
                    int hrow = (nt * 8 + lq) * QS_S + s * 8 + lr;
                    B[nt][0] = __float_as_uint(Qs[hrow]);
                    B[nt][1] = __float_as_uint(Qs[hrow + 4]);
                }
#pragma unroll
                for (int nt = 0; nt < 8; nt++) mma8(acc[nt], A, B[nt]);
            }
            __syncthreads();
        }
        // epilogue: exp -> fp16 staging (stride 36 u32, conflict-free) -> coalesced STG
        uint32_t* Pst = (uint32_t*)sm;
        const int r0l = w * 16 + lq, r1l = r0l + 8;
        const bool ok0 = (n0 + r0l) < NN, ok1 = (n0 + r1l) < NN;
#pragma unroll
        for (int nt = 0; nt < 8; nt++) {
            const int h = nt * 8 + 2 * lr;
            const float b0 = sbk[h], b1 = sbk[h + 1];
            float p0 = 0.f, p1 = 0.f, p2 = 0.f, p3 = 0.f;
            if (ok0) {
                p0 = __expf(acc[nt][0] * SCALE + b0);
                p1 = __expf(acc[nt][1] * SCALE + b1);
                sumacc[nt][0] += p0; sumacc[nt][1] += p1;
            }
            if (ok1) {
                p2 = __expf(acc[nt][2] * SCALE + b0);
                p3 = __expf(acc[nt][3] * SCALE + b1);
                sumacc[nt][0] += p2; sumacc[nt][1] += p3;
            }
            Pst[r0l * 36 + nt * 4 + lr] = pkh2(p0, p1);
            Pst[r1l * 36 + nt * 4 + lr] = pkh2(p2, p3);
        }
        __syncthreads();
#pragma unroll
        for (int j = 0; j < 4; j++) {
            int idx = t + j * 256, row = idx >> 3, c4 = (idx & 7) * 4;
            int gn = n0 + row;
            if (gn < NN) {
                uint4 v = *(uint4*)(Pst + row * 36 + c4);
                *(uint4*)(g_Ph + (size_t)gn * 32 + c4) = v;
            }
        }
        __syncthreads();
    }
#pragma unroll
    for (int off = 4; off <= 16; off <<= 1)
#pragma unroll
        for (int nt = 0; nt < 8; nt++) {
            sumacc[nt][0] += __shfl_xor_sync(0xffffffffu, sumacc[nt][0], off);
            sumacc[nt][1] += __shfl_xor_sync(0xffffffffu, sumacc[nt][1], off);
        }
    if (lane < 4)
#pragma unroll
        for (int nt = 0; nt < 8; nt++) {
            sums[w][nt * 8 + 2 * lane] = sumacc[nt][0];
            sums[w][nt * 8 + 2 * lane + 1] = sumacc[nt][1];
        }
    __syncthreads();
    if (t < KK) {
        float s = 0.f;
#pragma unroll
        for (int ww = 0; ww < 8; ww++) s += sums[ww][t];
        g_sumpart[blockIdx.x * 64 + t] = s;
    }
}

// ---- K2: pool GEMM, fp16 P in A operand ----
// smem: Ps x2 (u32[32][36]=1152 each) | Es x2 (fl[32][264]=8448 each) = 76800 B
#define PM_SMEM 76800
__global__ __launch_bounds__(256) void poolmma_kernel(const float* __restrict__ e) {
    extern __shared__ float sm2[];
    uint32_t* Psu = (uint32_t*)sm2;
    float* EsB[2] = {sm2 + 2304, sm2 + 10752};
    const uint32_t sbase = smem_u32(sm2);
    const int t = threadIdx.x, w = t >> 5, lane = t & 31;
    const int lq = lane >> 2, lr = lane & 3;
    const int dhalf = blockIdx.x & 1, slice = blockIdx.x >> 1;
    const int nbeg = slice * PSL;
    int nch = 0;
    if (nbeg < NN) { int r = (NN - nbeg + 31) / 32; nch = r < PSL_CH ? r : PSL_CH; }

    float acc[4][4][4];
#pragma unroll
    for (int mt = 0; mt < 4; mt++)
#pragma unroll
        for (int nt = 0; nt < 4; nt++)
#pragma unroll
            for (int i = 0; i < 4; i++) acc[mt][nt][i] = 0.f;

    if (nch > 0) {
#pragma unroll
        for (int j = 0; j < 8; j++) {
            int idx = t + j * 256, row = idx >> 6, c4 = idx & 63;
            int gn = nbeg + row;
            uint32_t dst = sbase + (2304 + row * 264 + c4 * 4) * 4;
            if (gn < NN) cpa16(dst, e + (size_t)gn * DD + dhalf * 256 + c4 * 4);
            else *(float4*)(EsB[0] + row * 264 + c4 * 4) = make_float4(0.f, 0.f, 0.f, 0.f);
        }
        {
            int row = t >> 3, c4 = (t & 7) * 4;
            int gn = nbeg + row;
            uint32_t dst = sbase + (row * 36 + c4) * 4;
            if (gn < NN) cpa16(dst, g_Ph + (size_t)gn * 32 + c4);
            else *(uint4*)(Psu + row * 36 + c4) = make_uint4(0, 0, 0, 0);
        }
        asm volatile("cp.async.commit_group;" ::: "memory");

        for (int c = 0; c < nch; c++) {
            const int b = c & 1;
            if (c + 1 < nch) {
                const int nb2 = (c + 1) & 1;
                const int n1 = nbeg + (c + 1) * 32;
#pragma unroll
                for (int j = 0; j < 8; j++) {
                    int idx = t + j * 256, row = idx >> 6, c4 = idx & 63;
                    int gn = n1 + row;
                    uint32_t dst = sbase + ((2304 + nb2 * 8448) + row * 264 + c4 * 4) * 4;
                    if (gn < NN) cpa16(dst, e + (size_t)gn * DD + dhalf * 256 + c4 * 4);
                    else *(float4*)(EsB[nb2] + row * 264 + c4 * 4) = make_float4(0.f, 0.f, 0.f, 0.f);
                }
                {
                    int row = t >> 3, c4 = (t & 7) * 4;
                    int gn = n1 + row;
                    uint32_t dst = sbase + (nb2 * 1152 + row * 36 + c4) * 4;
                    if (gn < NN) cpa16(dst, g_Ph + (size_t)gn * 32 + c4);
                    else *(uint4*)(Psu + nb2 * 1152 + row * 36 + c4) = make_uint4(0, 0, 0, 0);
                }
                asm volatile("cp.async.commit_group;" ::: "memory");
                asm volatile("cp.async.wait_group 1;" ::: "memory");
            } else {
                asm volatile("cp.async.wait_group 0;" ::: "memory");
            }
            __syncthreads();
            const uint32_t* Ps = Psu + b * 1152;
            const float* Es = EsB[b];
            const int hsel = lq & 1, hq = lq >> 1;
#pragma unroll
            for (int s = 0; s < 4; s++) {
                uint32_t A[4][4], B[4][2];
#pragma unroll
                for (int mt = 0; mt < 4; mt++) {
                    uint32_t w0 = Ps[(s * 8 + lr) * 36 + mt * 8 + hq];
                    uint32_t w1 = Ps[(s * 8 + lr) * 36 + mt * 8 + 4 + hq];
                    uint32_t w2 = Ps[(s * 8 + 4 + lr) * 36 + mt * 8 + hq];
                    uint32_t w3 = Ps[(s * 8 + 4 + lr) * 36 + mt * 8 + 4 + hq];
                    A[mt][0] = h2f(w0, hsel);
                    A[mt][1] = h2f(w1, hsel);
                    A[mt][2] = h2f(w2, hsel);
                    A[mt][3] = h2f(w3, hsel);
                }
#pragma unroll
                for (int nt = 0; nt < 4; nt++) {
                    int dcol = w * 32 + nt * 8 + lq;
                    B[nt][0] = __float_as_uint(Es[(s * 8 + lr) * 264 + dcol]);
                    B[nt][1] = __float_as_uint(Es[(s * 8 + 4 + lr) * 264 + dcol]);
                }
#pragma unroll
                for (int mt = 0; mt < 4; mt++)
#pragma unroll
                    for (int nt = 0; nt < 4; nt++) mma8(acc[mt][nt], A[mt], B[nt]);
            }
            __syncthreads();
        }
    }
    float* dst = g_part2 + (size_t)blockIdx.x * (64 * 256);
#pragma unroll
    for (int mt = 0; mt < 4; mt++)
#pragma unroll
        for (int nt = 0; nt < 4; nt++) {
            int head = mt * 16 + lq, d = w * 32 + nt * 8 + 2 * lr;
            *(float2*)(dst + head * 256 + d)       = make_float2(acc[mt][nt][0], acc[mt][nt][1]);
            *(float2*)(dst + (head + 8) * 256 + d) = make_float2(acc[mt][nt][2], acc[mt][nt][3]);
        }
}

// ---- K3: reduce (256 CTAs) ----
__global__ __launch_bounds__(128) void pool_reduce_kernel() {
    const int k = blockIdx.x >> 2, qq = blockIdx.x & 3;
    const int d = qq * 128 + threadIdx.x;
    const int dhalf = d >> 8, dl = d & 255;
    float s = 0.f;
    for (int sl = 0; sl < 148; sl++)
        s += g_part2[(size_t)(sl * 2 + dhalf) * (64 * 256) + k * 256 + dl];
    g_pooled[k * DD + d] = s;
}

// ---- K4: final (coalesced Wv) ----
__global__ __launch_bounds__(256) void final_kernel(const float* __restrict__ Wv,
        const float* __restrict__ bv, const float* __restrict__ mu_w,
        const float* __restrict__ mu_b, const float* __restrict__ sigma_w,
        const float* __restrict__ sigma_b, float* __restrict__ out) {
    const int k = blockIdx.x, t = threadIdx.x, w = t >> 5, lane = t & 31;
    __shared__ float red[256]; __shared__ float ps[DD]; __shared__ float hm[HH];
    float s = 0.f;
    for (int b = t; b < SGRID; b += 256) s += g_sumpart[b * 64 + k];
    red[t] = s;
    __syncthreads();
    for (int o = 128; o > 0; o >>= 1) { if (t < o) red[t] += red[t + o]; __syncthreads(); }
    float inv = 1.f / red[0];
    for (int d = t; d < DD; d += 256) ps[d] = g_pooled[k * DD + d] * inv;
    __syncthreads();
    for (int i = 0; i < 32; i++) {
        const int h = w * 32 + i;
        const float* wr = Wv + (size_t)k * HH * DD + (size_t)h * DD;
        float a = 0.f;
#pragma unroll
        for (int j = 0; j < 4; j++) {
            const int d = lane * 4 + j * 128;
            float4 v = *(const float4*)(wr + d);
            a += ps[d] * v.x + ps[d + 1] * v.y + ps[d + 2] * v.z + ps[d + 3] * v.w;
        }
#pragma unroll
        for (int o = 16; o > 0; o >>= 1) a += __shfl_xor_sync(0xffffffffu, a, o);
        if (lane == 0) hm[h] = a + bv[k * HH + h];
    }
    __syncthreads();
    float h = hm[t];
    float m = h * mu_w[t], g = h * sigma_w[t];
    red[t] = m;
    __syncthreads();
    for (int o = 128; o > 0; o >>= 1) { if (t < o) red[t] += red[t + o]; __syncthreads(); }
    float mu = red[0] + mu_b[0];
    __syncthreads();
    red[t] = g;
    __syncthreads();
    for (int o = 128; o > 0; o >>= 1) { if (t < o) red[t] += red[t + o]; __syncthreads(); }
    if (t == 0) { out[k] = mu; out[KK + k] = expf(red[0] + sigma_b[0]); }
}

extern "C" void kernel_launch(void* const* d_in, const int* in_sizes, int n_in,
                              void* d_out, int out_size) {
    const float* e       = (const float*)d_in[0];
    const float* q       = (const float*)d_in[1];
    const float* Wk      = (const float*)d_in[2];
    const float* bk      = (const float*)d_in[3];
    const float* Wv      = (const float*)d_in[4];
    const float* bv      = (const float*)d_in[5];
    const float* mu_w    = (const float*)d_in[6];
    const float* mu_b    = (const float*)d_in[7];
    const float* sigma_w = (const float*)d_in[8];
    const float* sigma_b = (const float*)d_in[9];
    float* out = (float*)d_out;

    cudaFuncSetAttribute(score_kernel, cudaFuncAttributeMaxDynamicSharedMemorySize, SC_SMEM);
    cudaFuncSetAttribute(poolmma_kernel, cudaFuncAttributeMaxDynamicSharedMemorySize, PM_SMEM);
    prep_kernel<<<KK, 512>>>(q, Wk, bk);
    score_kernel<<<SGRID, 256, SC_SMEM>>>(e);
    poolmma_kernel<<<296, 256, PM_SMEM>>>(e);
    pool_reduce_kernel<<<256, 128>>>();
    final_kernel<<<KK, 256>>>(Wv, bv, mu_w, mu_b, sigma_w, sigma_b, out);
}